// round 6
// baseline (speedup 1.0000x reference)
#include <cuda_runtime.h>
#include <math.h>

#define BB   4
#define NBLK 256
#define LL   64
#define KK   65
#define CCH  512
#define HH   8
#define HD   64
#define SCALE 0.125f

// Scratch (device globals: the sanctioned alloc-free path). 16B-aligned for float4.
__device__ __align__(16) float g_bm[BB * NBLK * CCH];                   //   2 MB block means
__device__ __align__(16) float g_qkv[(size_t)BB * NBLK * KK * 3 * CCH]; // 409 MB fused qkv
__device__ __align__(16) float g_o[(size_t)BB * NBLK * LL * CCH];       // 128 MB attention out

// ---------------------------------------------------------------------------
// 1) block-node means: one CTA per (b,nb), thread = channel
// ---------------------------------------------------------------------------
__global__ void mean_kernel(const float* __restrict__ x) {
    int blk = blockIdx.x;          // 0..1023  (b*NB + nb)
    int c   = threadIdx.x;         // 0..511
    const float* xr = x + (size_t)blk * LL * CCH + c;
    float s = 0.f;
#pragma unroll
    for (int i = 0; i < LL; i++) s += xr[(size_t)i * CCH];
    g_bm[(size_t)blk * CCH + c] = s * (1.0f / LL);
}

// ---------------------------------------------------------------------------
// 2/4) 128x128x8 SIMT sgemm, 256 threads, 8x8 microtile.
//  MODE 0: QKV  — A row r: blk=r/65, pos=r%65 -> x row or mean row. C = g_qkv. N=1536
//  MODE 1: proj — A = g_o. C = param.                                        N=512
// ---------------------------------------------------------------------------
template <int MODE>
__global__ void sgemm128(const float* __restrict__ A,
                         const float* __restrict__ Bm,
                         const float* __restrict__ bias,
                         float* __restrict__ Cm) {
    constexpr int N  = (MODE == 0) ? 1536 : 512;
    constexpr int Kd = 512;

    __shared__ float As[8][132];
    __shared__ float Bs[8][132];

    int tid  = threadIdx.x;
    int tx   = tid & 15;            // 0..15
    int ty   = tid >> 4;            // 0..15
    int arow = tid >> 1;            // 0..127
    int acol = (tid & 1) * 4;
    int brow = tid >> 5;            // 0..7
    int bcol = (tid & 31) * 4;

    long mrow = (long)blockIdx.y * 128 + arow;
    const float* ap;
    if (MODE == 0) {
        long blk = mrow / 65;
        long pos = mrow - blk * 65;
        ap = (pos < 64) ? (A + (blk * 64 + pos) * (long)Kd)
                        : (g_bm + blk * (long)Kd);
    } else {
        ap = g_o + mrow * (long)Kd;
    }
    const float* bp = Bm + (long)blockIdx.x * 128;

    float acc[8][8];
#pragma unroll
    for (int i = 0; i < 8; i++)
#pragma unroll
        for (int j = 0; j < 8; j++) acc[i][j] = 0.f;

    for (int k0 = 0; k0 < Kd; k0 += 8) {
        float4 av = *(const float4*)(ap + k0 + acol);
        As[acol + 0][arow] = av.x;
        As[acol + 1][arow] = av.y;
        As[acol + 2][arow] = av.z;
        As[acol + 3][arow] = av.w;
        *(float4*)(&Bs[brow][bcol]) =
            *(const float4*)(bp + (long)(k0 + brow) * N + bcol);
        __syncthreads();
#pragma unroll
        for (int k = 0; k < 8; k++) {
            float a[8], b[8];
            *(float4*)(a)     = *(float4*)(&As[k][ty * 8]);
            *(float4*)(a + 4) = *(float4*)(&As[k][ty * 8 + 4]);
            *(float4*)(b)     = *(float4*)(&Bs[k][tx * 8]);
            *(float4*)(b + 4) = *(float4*)(&Bs[k][tx * 8 + 4]);
#pragma unroll
            for (int i = 0; i < 8; i++)
#pragma unroll
                for (int j = 0; j < 8; j++) acc[i][j] += a[i] * b[j];
        }
        __syncthreads();
    }

    float* cdst = (MODE == 0) ? g_qkv : Cm;
    long crow0  = (long)blockIdx.y * 128 + ty * 8;
    int  ccol   = blockIdx.x * 128 + tx * 8;
    float bv[8];
#pragma unroll
    for (int j = 0; j < 8; j++) bv[j] = bias[ccol + j];
#pragma unroll
    for (int i = 0; i < 8; i++) {
        float4 r0 = make_float4(acc[i][0] + bv[0], acc[i][1] + bv[1],
                                acc[i][2] + bv[2], acc[i][3] + bv[3]);
        float4 r1 = make_float4(acc[i][4] + bv[4], acc[i][5] + bv[5],
                                acc[i][6] + bv[6], acc[i][7] + bv[7]);
        *(float4*)(cdst + (crow0 + i) * (long)N + ccol)     = r0;
        *(float4*)(cdst + (crow0 + i) * (long)N + ccol + 4) = r1;
    }
}

// ---------------------------------------------------------------------------
// 3) attention: one CTA per (b*NB+nb, head). 256 threads (8 warps).
//    warp w handles query rows w*8..w*8+7; lane handles keys {lane, lane+32, 64}
//    mask is read as 4-byte words (bool promoted to int32 or float32 by the
//    harness): nonzero bit pattern == True for both encodings.
// ---------------------------------------------------------------------------
#define KS_FLOATS (65 * 65 + 3)   // pad so vs is 16B-aligned
#define ATTN_SMEM_FLOATS (64 * 64 + KS_FLOATS + 65 * 64 + 64 * 66)

__global__ void attn_kernel(const int* __restrict__ mask,
                            const float* __restrict__ ef) {
    extern __shared__ float sm[];
    float* qs = sm;                  // 64 x 64            (stride 64)
    float* ks = qs + 64 * 64;        // 65 x 64, stride 65 (conflict-free dot)
    float* vs = ks + KS_FLOATS;      // 65 x 64            (stride 64), 16B-aligned
    float* ps = vs + 65 * 64;        // 64 x 66 probs

    int bh  = blockIdx.x;
    int h   = bh & (HH - 1);
    int blk = bh >> 3;              // b*NB + nb
    int nb  = blk & (NBLK - 1);
    int tid = threadIdx.x;
    int w   = tid >> 5;
    int lane = tid & 31;

    const float* qbase = g_qkv + (size_t)blk * 65 * 1536 + h * 64;
    const float* kbase = qbase + 512;
    const float* vbase = qbase + 1024;

    for (int idx = tid; idx < 64 * 16; idx += 256) {
        int r = idx >> 4, c4 = (idx & 15) << 2;
        *(float4*)(qs + r * 64 + c4) = *(const float4*)(qbase + (size_t)r * 1536 + c4);
    }
    for (int idx = tid; idx < 65 * 16; idx += 256) {
        int r = idx >> 4, c4 = (idx & 15) << 2;
        float4 v = *(const float4*)(kbase + (size_t)r * 1536 + c4);
        float* d = ks + r * 65 + c4;
        d[0] = v.x; d[1] = v.y; d[2] = v.z; d[3] = v.w;
    }
    for (int idx = tid; idx < 65 * 16; idx += 256) {
        int r = idx >> 4, c4 = (idx & 15) << 2;
        *(float4*)(vs + r * 64 + c4) = *(const float4*)(vbase + (size_t)r * 1536 + c4);
    }
    __syncthreads();

    int j0 = lane, j1 = lane + 32;   // j2 = 64 (broadcast, identical per lane)
    float acc0[8], acc1[8], acc2[8];
#pragma unroll
    for (int r = 0; r < 8; r++) { acc0[r] = 0.f; acc1[r] = 0.f; acc2[r] = 0.f; }

    for (int kk = 0; kk < 64; kk++) {
        float k0v = ks[j0 * 65 + kk];
        float k1v = ks[j1 * 65 + kk];
        float k2v = ks[64 * 65 + kk];
#pragma unroll
        for (int r = 0; r < 8; r++) {
            float qv = qs[(w * 8 + r) * 64 + kk];
            acc0[r] = fmaf(qv, k0v, acc0[r]);
            acc1[r] = fmaf(qv, k1v, acc1[r]);
            acc2[r] = fmaf(qv, k2v, acc2[r]);
        }
    }

#pragma unroll
    for (int r = 0; r < 8; r++) {
        int i = w * 8 + r;
        size_t mbase = ((size_t)nb * 64 + i) * 65;
        float b0 = (j0 == i) ? 1.0f : ef[(mbase + j0) * 4 + 3];
        float b1 = (j1 == i) ? 1.0f : ef[(mbase + j1) * 4 + 3];
        float s0 = (mask[mbase + j0] != 0) ? fmaf(acc0[r], SCALE, b0) : -1e9f;
        float s1 = (mask[mbase + j1] != 0) ? fmaf(acc1[r], SCALE, b1) : -1e9f;
        float s2 = fmaf(acc2[r], SCALE, 1.0f);   // j=64: mask forced true, bias 1

        float m = fmaxf(fmaxf(s0, s1), s2);
#pragma unroll
        for (int o = 16; o > 0; o >>= 1) m = fmaxf(m, __shfl_xor_sync(0xffffffffu, m, o));
        float e0 = __expf(s0 - m), e1 = __expf(s1 - m), e2 = __expf(s2 - m);
        float sum = e0 + e1;
#pragma unroll
        for (int o = 16; o > 0; o >>= 1) sum += __shfl_xor_sync(0xffffffffu, sum, o);
        sum += e2;                                // j=64 counted once
        float inv = 1.0f / sum;
        float* prow = ps + i * 66;
        prow[j0] = e0 * inv;
        prow[j1] = e1 * inv;
        if (lane == 0) prow[64] = e2 * inv;
    }
    __syncwarp();

    float o0[8], o1[8];
#pragma unroll
    for (int r = 0; r < 8; r++) { o0[r] = 0.f; o1[r] = 0.f; }
    for (int j = 0; j < 65; j++) {
        float v0 = vs[j * 64 + lane];
        float v1 = vs[j * 64 + lane + 32];
#pragma unroll
        for (int r = 0; r < 8; r++) {
            float p = ps[(w * 8 + r) * 66 + j];
            o0[r] = fmaf(p, v0, o0[r]);
            o1[r] = fmaf(p, v1, o1[r]);
        }
    }
    float* obase = g_o + (size_t)blk * 64 * 512 + h * 64;
#pragma unroll
    for (int r = 0; r < 8; r++) {
        obase[(size_t)(w * 8 + r) * 512 + lane]      = o0[r];
        obase[(size_t)(w * 8 + r) * 512 + lane + 32] = o1[r];
    }
}

// ---------------------------------------------------------------------------
extern "C" void kernel_launch(void* const* d_in, const int* in_sizes, int n_in,
                              void* d_out, int out_size) {
    const float* x      = (const float*)d_in[0];
    const int*   mask   = (const int*)d_in[1];     // bool promoted to 4-byte
    const float* ef     = (const float*)d_in[2];
    const float* qkv_w  = (const float*)d_in[3];
    const float* qkv_b  = (const float*)d_in[4];
    const float* proj_w = (const float*)d_in[5];
    const float* proj_b = (const float*)d_in[6];
    float*       out    = (float*)d_out;

    (void)in_sizes; (void)n_in; (void)out_size;

    const int ATTN_SMEM = ATTN_SMEM_FLOATS * 4;   // 66832 B
    cudaFuncSetAttribute(attn_kernel, cudaFuncAttributeMaxDynamicSharedMemorySize,
                         ATTN_SMEM);

    mean_kernel<<<BB * NBLK, CCH>>>(x);
    // QKV: M = 1024*65 = 66560 = 520*128, N = 1536 = 12*128
    sgemm128<0><<<dim3(12, 520), 256>>>(x, qkv_w, qkv_b, nullptr);
    // attention: 1024 blocks * 8 heads
    attn_kernel<<<BB * NBLK * HH, 256, ATTN_SMEM>>>(mask, ef);
    // proj: M = 65536 = 512*128, N = 512 = 4*128
    sgemm128<1><<<dim3(4, 512), 256>>>(nullptr, proj_w, proj_b, out);
}

// round 12
// speedup vs baseline: 2.4622x; 2.4622x over previous
#include <cuda_runtime.h>
#include <cuda_bf16.h>
#include <cstdint>
#include <math.h>

#define BB   4
#define NBLK 256
#define LL   64
#define KK   65
#define CCH  512
#define HH   8
#define SCALE 0.125f

// ---------------- scratch (device globals; 16B aligned) ----------------
__device__ __align__(16) float g_bm[BB * NBLK * CCH];                        // 2 MB
__device__ __align__(16) float g_qkv[(size_t)BB * NBLK * KK * 3 * CCH];      // 409 MB
__device__ __align__(16) __nv_bfloat16 g_akvh[(size_t)BB * NBLK * KK * CCH]; // 68 MB
__device__ __align__(16) __nv_bfloat16 g_akvl[(size_t)BB * NBLK * KK * CCH];
__device__ __align__(16) __nv_bfloat16 g_aoh[(size_t)BB * NBLK * LL * CCH];  // 67 MB
__device__ __align__(16) __nv_bfloat16 g_aol[(size_t)BB * NBLK * LL * CCH];
__device__ __align__(16) __nv_bfloat16 g_wqkvTh[3 * CCH * CCH];              // [1536][512]
__device__ __align__(16) __nv_bfloat16 g_wqkvTl[3 * CCH * CCH];
__device__ __align__(16) __nv_bfloat16 g_wprojTh[CCH * CCH];                 // [512][512]
__device__ __align__(16) __nv_bfloat16 g_wprojTl[CCH * CCH];

// ---------------- helpers (sm_80-era instructions only: compile-safe) -------
__device__ __forceinline__ uint32_t smem_u32(const void* p) {
    uint32_t a;
    asm("{ .reg .u64 t; cvta.to.shared.u64 t, %1; cvt.u32.u64 %0, t; }" : "=r"(a) : "l"(p));
    return a;
}
__device__ __forceinline__ void cp16(uint32_t s, const void* g) {
    asm volatile("cp.async.cg.shared.global [%0], [%1], 16;" :: "r"(s), "l"(g));
}
__device__ __forceinline__ void ldsm4(uint32_t* r, uint32_t a) {
    asm volatile("ldmatrix.sync.aligned.m8n8.x4.shared.b16 {%0,%1,%2,%3}, [%4];"
        : "=r"(r[0]), "=r"(r[1]), "=r"(r[2]), "=r"(r[3]) : "r"(a));
}
__device__ __forceinline__ void mma16816(float* d, const uint32_t* a, const uint32_t* b) {
    asm volatile("mma.sync.aligned.m16n8k16.row.col.f32.bf16.bf16.f32 "
        "{%0,%1,%2,%3}, {%4,%5,%6,%7}, {%8,%9}, {%0,%1,%2,%3};"
        : "+f"(d[0]), "+f"(d[1]), "+f"(d[2]), "+f"(d[3])
        : "r"(a[0]), "r"(a[1]), "r"(a[2]), "r"(a[3]), "r"(b[0]), "r"(b[1]));
}

// ---------------- 1) block means ----------------
__global__ void mean_kernel(const float* __restrict__ x) {
    int blk = blockIdx.x;
    int c   = threadIdx.x;
    const float* xr = x + (size_t)blk * LL * CCH + c;
    float s = 0.f;
#pragma unroll
    for (int i = 0; i < LL; i++) s += xr[(size_t)i * CCH];
    g_bm[(size_t)blk * CCH + c] = s * (1.0f / LL);
}

// ---------------- 2) kv rows -> bf16 hi/lo (gather + split) ----------------
__global__ void kvprep(const float* __restrict__ x) {
    size_t r = blockIdx.x;                  // 0..66559
    int t = threadIdx.x;                    // 0..127, 4 floats each
    size_t blk = r / 65, pos = r - blk * 65;
    const float* src = (pos < 64) ? (x + (blk * 64 + pos) * (size_t)CCH)
                                  : (g_bm + blk * (size_t)CCH);
    float4 v = *(const float4*)(src + t * 4);
    float f[4] = {v.x, v.y, v.z, v.w};
    __nv_bfloat16 hi[4], lo[4];
#pragma unroll
    for (int i = 0; i < 4; i++) {
        hi[i] = __float2bfloat16_rn(f[i]);
        lo[i] = __float2bfloat16_rn(f[i] - __bfloat162float(hi[i]));
    }
    __nv_bfloat162* dh = (__nv_bfloat162*)(g_akvh + r * CCH + t * 4);
    __nv_bfloat162* dl = (__nv_bfloat162*)(g_akvl + r * CCH + t * 4);
    dh[0] = __nv_bfloat162{hi[0], hi[1]}; dh[1] = __nv_bfloat162{hi[2], hi[3]};
    dl[0] = __nv_bfloat162{lo[0], lo[1]}; dl[1] = __nv_bfloat162{lo[2], lo[3]};
}

// ---------------- 3) weight transpose + split: w[512][N] -> wT[N][512] hi/lo ----
__global__ void wprep(const float* __restrict__ w, __nv_bfloat16* __restrict__ oh,
                      __nv_bfloat16* __restrict__ ol, int N) {
    __shared__ float t[32][33];
    int n0 = blockIdx.x * 32, k0 = blockIdx.y * 32;
    int tx = threadIdx.x, ty = threadIdx.y;     // (32, 8)
#pragma unroll
    for (int j = 0; j < 4; j++)
        t[ty * 4 + j][tx] = w[(size_t)(k0 + ty * 4 + j) * N + n0 + tx];
    __syncthreads();
#pragma unroll
    for (int j = 0; j < 4; j++) {
        float v = t[tx][ty * 4 + j];
        __nv_bfloat16 hi = __float2bfloat16_rn(v);
        __nv_bfloat16 lo = __float2bfloat16_rn(v - __bfloat162float(hi));
        size_t idx = (size_t)(n0 + ty * 4 + j) * CCH + k0 + tx;
        oh[idx] = hi; ol[idx] = lo;
    }
}

// ---------------- 4) split-bf16 3-pass GEMM via mma.sync ---------------------
// C[M][NT] = A[M][512] @ W[NT][512]^T + bias.  CTA 128x128, 8 warps (4M x 2N),
// warp tile 32x64, K-chunk 64, 2-stage cp.async double buffer.
// Stage layout (64 KB): Ah @0, Al @16K, Bh @32K, Bl @48K; rows 128B, XOR-swizzled.
#define GSTAGE 65536
#define GEMM_SMEM (2 * GSTAGE)

template <int NT>
__global__ __launch_bounds__(256)
void gemm_mma3(const __nv_bfloat16* __restrict__ Ah, const __nv_bfloat16* __restrict__ Al,
               const __nv_bfloat16* __restrict__ Wh, const __nv_bfloat16* __restrict__ Wl,
               const float* __restrict__ bias, float* __restrict__ C) {
    extern __shared__ __align__(16) char smem[];
    uint32_t sb = smem_u32(smem);
    int tid = threadIdx.x, lane = tid & 31, wid = tid >> 5;
    int g = lane >> 2, t4 = lane & 3;
    int wm = (wid >> 1) * 32, wn = (wid & 1) * 64;
    size_t m0 = (size_t)blockIdx.y * 128;
    int n0 = blockIdx.x * 128;

    float acc[2][8][4];
#pragma unroll
    for (int i = 0; i < 2; i++)
#pragma unroll
        for (int j = 0; j < 8; j++)
#pragma unroll
            for (int q = 0; q < 4; q++) acc[i][j][q] = 0.f;

    // loader slots: 4 x 16B per thread per tile
    uint32_t soff[4];
    size_t aoff[4], boff[4];
#pragma unroll
    for (int i = 0; i < 4; i++) {
        int l = tid + i * 256;            // 0..1023
        int row = l >> 3, ch = l & 7;
        soff[i] = (uint32_t)(row * 128 + ((ch ^ (row & 7)) << 4));
        aoff[i] = (m0 + row) * CCH + ch * 8;
        boff[i] = (size_t)(n0 + row) * CCH + ch * 8;
    }

    // ldmatrix lane addressing
    int lt = lane >> 3, lr = lane & 7;
    int amrow[2];
#pragma unroll
    for (int mi = 0; mi < 2; mi++) amrow[mi] = wm + mi * 16 + ((lt & 1) << 3) + lr;
    int a_chadd = lt >> 1;
    int bnrow[4];
#pragma unroll
    for (int bb = 0; bb < 4; bb++) bnrow[bb] = wn + bb * 16 + ((lt >> 1) << 3) + lr;
    int b_chadd = lt & 1;

#define LOAD_STAGE(stg, ko)                                                        \
    {                                                                              \
        uint32_t st_ = sb + (uint32_t)(stg) * GSTAGE;                              \
        _Pragma("unroll")                                                          \
        for (int i_ = 0; i_ < 4; i_++) {                                           \
            cp16(st_ + soff[i_],          Ah + aoff[i_] + (ko));                   \
            cp16(st_ + 16384 + soff[i_],  Al + aoff[i_] + (ko));                   \
            cp16(st_ + 32768 + soff[i_],  Wh + boff[i_] + (ko));                   \
            cp16(st_ + 49152 + soff[i_],  Wl + boff[i_] + (ko));                   \
        }                                                                          \
        asm volatile("cp.async.commit_group;" ::: "memory");                       \
    }

    LOAD_STAGE(0, 0);

    for (int c = 0; c < 8; c++) {
        asm volatile("cp.async.wait_group 0;" ::: "memory");
        __syncthreads();
        if (c < 7) LOAD_STAGE((c + 1) & 1, (c + 1) * 64);

        uint32_t st = sb + (uint32_t)(c & 1) * GSTAGE;
#pragma unroll
        for (int ks = 0; ks < 4; ks++) {
            int cb = ks * 2;
            uint32_t ah[2][4], al[2][4], bh[8][2], bl[8][2];
#pragma unroll
            for (int mi = 0; mi < 2; mi++) {
                int r = amrow[mi];
                uint32_t ad = st + r * 128 + (((cb + a_chadd) ^ (r & 7)) << 4);
                ldsm4(ah[mi], ad);
                ldsm4(al[mi], ad + 16384);
            }
#pragma unroll
            for (int bb = 0; bb < 4; bb++) {
                int r = bnrow[bb];
                uint32_t bd = st + 32768 + r * 128 + (((cb + b_chadd) ^ (r & 7)) << 4);
                uint32_t rr[4];
                ldsm4(rr, bd);
                bh[2 * bb][0] = rr[0]; bh[2 * bb][1] = rr[1];
                bh[2 * bb + 1][0] = rr[2]; bh[2 * bb + 1][1] = rr[3];
                ldsm4(rr, bd + 16384);
                bl[2 * bb][0] = rr[0]; bl[2 * bb][1] = rr[1];
                bl[2 * bb + 1][0] = rr[2]; bl[2 * bb + 1][1] = rr[3];
            }
#pragma unroll
            for (int mi = 0; mi < 2; mi++)
#pragma unroll
                for (int ni = 0; ni < 8; ni++) {
                    mma16816(acc[mi][ni], ah[mi], bh[ni]);
                    mma16816(acc[mi][ni], ah[mi], bl[ni]);
                    mma16816(acc[mi][ni], al[mi], bh[ni]);
                }
        }
    }

    // epilogue: bias + fp32 store
#pragma unroll
    for (int ni = 0; ni < 8; ni++) {
        int col = n0 + wn + ni * 8 + t4 * 2;
        float b0 = bias[col], b1 = bias[col + 1];
#pragma unroll
        for (int mi = 0; mi < 2; mi++) {
            size_t r0 = m0 + wm + mi * 16 + g;
            float2 v0 = make_float2(acc[mi][ni][0] + b0, acc[mi][ni][1] + b1);
            float2 v1 = make_float2(acc[mi][ni][2] + b0, acc[mi][ni][3] + b1);
            *(float2*)(C + r0 * NT + col)       = v0;
            *(float2*)(C + (r0 + 8) * NT + col) = v1;
        }
    }
}

// ---------------- 5) attention (fp32; emits bf16 hi/lo for proj) -------------
#define KS_FLOATS (65 * 65 + 3)
#define ATTN_SMEM_FLOATS (64 * 64 + KS_FLOATS + 65 * 64 + 64 * 66)

__global__ void attn_kernel(const int* __restrict__ mask,
                            const float* __restrict__ ef) {
    extern __shared__ float sm[];
    float* qs = sm;
    float* ks = qs + 64 * 64;
    float* vs = ks + KS_FLOATS;
    float* ps = vs + 65 * 64;

    int bh  = blockIdx.x;
    int hd  = bh & (HH - 1);
    int blk = bh >> 3;
    int nb  = blk & (NBLK - 1);
    int tid = threadIdx.x;
    int w   = tid >> 5;
    int lane = tid & 31;

    const float* qbase = g_qkv + (size_t)blk * 65 * 1536 + hd * 64;
    const float* kbase = qbase + 512;
    const float* vbase = qbase + 1024;

    for (int idx = tid; idx < 64 * 16; idx += 256) {
        int r = idx >> 4, c4 = (idx & 15) << 2;
        *(float4*)(qs + r * 64 + c4) = *(const float4*)(qbase + (size_t)r * 1536 + c4);
    }
    for (int idx = tid; idx < 65 * 16; idx += 256) {
        int r = idx >> 4, c4 = (idx & 15) << 2;
        float4 v = *(const float4*)(kbase + (size_t)r * 1536 + c4);
        float* d = ks + r * 65 + c4;
        d[0] = v.x; d[1] = v.y; d[2] = v.z; d[3] = v.w;
    }
    for (int idx = tid; idx < 65 * 16; idx += 256) {
        int r = idx >> 4, c4 = (idx & 15) << 2;
        *(float4*)(vs + r * 64 + c4) = *(const float4*)(vbase + (size_t)r * 1536 + c4);
    }
    __syncthreads();

    int j0 = lane, j1 = lane + 32;
    float acc0[8], acc1[8], acc2[8];
#pragma unroll
    for (int r = 0; r < 8; r++) { acc0[r] = 0.f; acc1[r] = 0.f; acc2[r] = 0.f; }

    for (int kk = 0; kk < 64; kk++) {
        float k0v = ks[j0 * 65 + kk];
        float k1v = ks[j1 * 65 + kk];
        float k2v = ks[64 * 65 + kk];
#pragma unroll
        for (int r = 0; r < 8; r++) {
            float qv = qs[(w * 8 + r) * 64 + kk];
            acc0[r] = fmaf(qv, k0v, acc0[r]);
            acc1[r] = fmaf(qv, k1v, acc1[r]);
            acc2[r] = fmaf(qv, k2v, acc2[r]);
        }
    }

#pragma unroll
    for (int r = 0; r < 8; r++) {
        int i = w * 8 + r;
        size_t mbase = ((size_t)nb * 64 + i) * 65;
        float b0 = (j0 == i) ? 1.0f : ef[(mbase + j0) * 4 + 3];
        float b1 = (j1 == i) ? 1.0f : ef[(mbase + j1) * 4 + 3];
        float s0 = (mask[mbase + j0] != 0) ? fmaf(acc0[r], SCALE, b0) : -1e9f;
        float s1 = (mask[mbase + j1] != 0) ? fmaf(acc1[r], SCALE, b1) : -1e9f;
        float s2 = fmaf(acc2[r], SCALE, 1.0f);

        float m = fmaxf(fmaxf(s0, s1), s2);
#pragma unroll
        for (int o = 16; o > 0; o >>= 1) m = fmaxf(m, __shfl_xor_sync(0xffffffffu, m, o));
        float e0 = __expf(s0 - m), e1 = __expf(s1 - m), e2 = __expf(s2 - m);
        float sum = e0 + e1;
#pragma unroll
        for (int o = 16; o > 0; o >>= 1) sum += __shfl_xor_sync(0xffffffffu, sum, o);
        sum += e2;
        float inv = 1.0f / sum;
        float* prow = ps + i * 66;
        prow[j0] = e0 * inv;
        prow[j1] = e1 * inv;
        if (lane == 0) prow[64] = e2 * inv;
    }
    __syncwarp();

    float o0[8], o1[8];
#pragma unroll
    for (int r = 0; r < 8; r++) { o0[r] = 0.f; o1[r] = 0.f; }
    for (int j = 0; j < 65; j++) {
        float v0 = vs[j * 64 + lane];
        float v1 = vs[j * 64 + lane + 32];
#pragma unroll
        for (int r = 0; r < 8; r++) {
            float p = ps[(w * 8 + r) * 66 + j];
            o0[r] = fmaf(p, v0, o0[r]);
            o1[r] = fmaf(p, v1, o1[r]);
        }
    }
#pragma unroll
    for (int r = 0; r < 8; r++) {
        size_t orow = (size_t)blk * 64 + (w * 8 + r);
        size_t c0 = orow * 512 + hd * 64 + lane;
        float va = o0[r], vb = o1[r];
        __nv_bfloat16 ha = __float2bfloat16_rn(va);
        __nv_bfloat16 hb = __float2bfloat16_rn(vb);
        g_aoh[c0]      = ha;
        g_aoh[c0 + 32] = hb;
        g_aol[c0]      = __float2bfloat16_rn(va - __bfloat162float(ha));
        g_aol[c0 + 32] = __float2bfloat16_rn(vb - __bfloat162float(hb));
    }
}

// ---------------------------------------------------------------------------
extern "C" void kernel_launch(void* const* d_in, const int* in_sizes, int n_in,
                              void* d_out, int out_size) {
    const float* x      = (const float*)d_in[0];
    const int*   mask   = (const int*)d_in[1];
    const float* ef     = (const float*)d_in[2];
    const float* qkv_w  = (const float*)d_in[3];
    const float* qkv_b  = (const float*)d_in[4];
    const float* proj_w = (const float*)d_in[5];
    const float* proj_b = (const float*)d_in[6];
    float*       out    = (float*)d_out;
    (void)in_sizes; (void)n_in; (void)out_size;

    const int ATTN_SMEM = ATTN_SMEM_FLOATS * 4;
    cudaFuncSetAttribute(attn_kernel, cudaFuncAttributeMaxDynamicSharedMemorySize, ATTN_SMEM);
    cudaFuncSetAttribute(gemm_mma3<1536>, cudaFuncAttributeMaxDynamicSharedMemorySize, GEMM_SMEM);
    cudaFuncSetAttribute(gemm_mma3<512>,  cudaFuncAttributeMaxDynamicSharedMemorySize, GEMM_SMEM);

    __nv_bfloat16 *akvh, *akvl, *aoh, *aol, *wqh, *wql, *wph, *wpl;
    cudaGetSymbolAddress((void**)&akvh, g_akvh);
    cudaGetSymbolAddress((void**)&akvl, g_akvl);
    cudaGetSymbolAddress((void**)&aoh,  g_aoh);
    cudaGetSymbolAddress((void**)&aol,  g_aol);
    cudaGetSymbolAddress((void**)&wqh,  g_wqkvTh);
    cudaGetSymbolAddress((void**)&wql,  g_wqkvTl);
    cudaGetSymbolAddress((void**)&wph,  g_wprojTh);
    cudaGetSymbolAddress((void**)&wpl,  g_wprojTl);
    float* qkv;
    cudaGetSymbolAddress((void**)&qkv, g_qkv);

    mean_kernel<<<BB * NBLK, CCH>>>(x);
    kvprep<<<BB * NBLK * KK, 128>>>(x);
    wprep<<<dim3(48, 16), dim3(32, 8)>>>(qkv_w, wqh, wql, 1536);
    wprep<<<dim3(16, 16), dim3(32, 8)>>>(proj_w, wph, wpl, 512);
    // QKV: M = 66560 = 520*128, N = 1536 = 12*128
    gemm_mma3<1536><<<dim3(12, 520), 256, GEMM_SMEM>>>(akvh, akvl, wqh, wql, qkv_b, qkv);
    attn_kernel<<<BB * NBLK * HH, 256, ATTN_SMEM>>>(mask, ef);
    // proj: M = 65536 = 512*128, N = 512 = 4*128
    gemm_mma3<512><<<dim3(4, 512), 256, GEMM_SMEM>>>(aoh, aol, wph, wpl, proj_b, out);
}

// round 14
// speedup vs baseline: 2.5527x; 1.0368x over previous
#include <cuda_runtime.h>
#include <cuda_bf16.h>
#include <cstdint>
#include <math.h>

#define BB   4
#define NBLK 256
#define LL   64
#define KK   65
#define CCH  512
#define HH   8
#define SCALE 0.125f

// ---------------- scratch (device globals; 16B aligned) ----------------
__device__ __align__(16) float g_qkv[(size_t)BB * NBLK * KK * 3 * CCH];      // 409 MB
__device__ __align__(16) __nv_bfloat16 g_akvh[(size_t)BB * NBLK * KK * CCH]; // 68 MB
__device__ __align__(16) __nv_bfloat16 g_akvl[(size_t)BB * NBLK * KK * CCH];
__device__ __align__(16) __nv_bfloat16 g_aoh[(size_t)BB * NBLK * LL * CCH];  // 67 MB
__device__ __align__(16) __nv_bfloat16 g_aol[(size_t)BB * NBLK * LL * CCH];
__device__ __align__(16) __nv_bfloat16 g_wqkvTh[3 * CCH * CCH];              // [1536][512]
__device__ __align__(16) __nv_bfloat16 g_wqkvTl[3 * CCH * CCH];
__device__ __align__(16) __nv_bfloat16 g_wprojTh[CCH * CCH];                 // [512][512]
__device__ __align__(16) __nv_bfloat16 g_wprojTl[CCH * CCH];

// ---------------- helpers (sm_80-era instructions only: compile-safe) -------
__device__ __forceinline__ uint32_t smem_u32(const void* p) {
    uint32_t a;
    asm("{ .reg .u64 t; cvta.to.shared.u64 t, %1; cvt.u32.u64 %0, t; }" : "=r"(a) : "l"(p));
    return a;
}
__device__ __forceinline__ void cp16(uint32_t s, const void* g) {
    asm volatile("cp.async.cg.shared.global [%0], [%1], 16;" :: "r"(s), "l"(g));
}
__device__ __forceinline__ void ldsm4(uint32_t* r, uint32_t a) {
    asm volatile("ldmatrix.sync.aligned.m8n8.x4.shared.b16 {%0,%1,%2,%3}, [%4];"
        : "=r"(r[0]), "=r"(r[1]), "=r"(r[2]), "=r"(r[3]) : "r"(a));
}
__device__ __forceinline__ void mma16816(float* d, const uint32_t* a, const uint32_t* b) {
    asm volatile("mma.sync.aligned.m16n8k16.row.col.f32.bf16.bf16.f32 "
        "{%0,%1,%2,%3}, {%4,%5,%6,%7}, {%8,%9}, {%0,%1,%2,%3};"
        : "+f"(d[0]), "+f"(d[1]), "+f"(d[2]), "+f"(d[3])
        : "r"(a[0]), "r"(a[1]), "r"(a[2]), "r"(a[3]), "r"(b[0]), "r"(b[1]));
}

// ---------------- 1) fused mean + kv split: one CTA per (b,nb) block ---------
// 256 threads; thread t owns channels {2t, 2t+1}. Reads x once, writes 65 rows
// of bf16 hi/lo (row 64 = block mean).
__global__ void kvprep2(const float* __restrict__ x) {
    int blk = blockIdx.x;                   // 0..1023
    int t = threadIdx.x;                    // 0..255
    const float* xb = x + (size_t)blk * LL * CCH + t * 2;
    size_t obase = (size_t)blk * KK * CCH + t * 2;
    float m0 = 0.f, m1 = 0.f;
#pragma unroll 4
    for (int r = 0; r < LL; r++) {
        float2 v = *(const float2*)(xb + (size_t)r * CCH);
        m0 += v.x; m1 += v.y;
        __nv_bfloat16 h0 = __float2bfloat16_rn(v.x);
        __nv_bfloat16 h1 = __float2bfloat16_rn(v.y);
        *(__nv_bfloat162*)(g_akvh + obase + (size_t)r * CCH) = __nv_bfloat162{h0, h1};
        *(__nv_bfloat162*)(g_akvl + obase + (size_t)r * CCH) =
            __nv_bfloat162{__float2bfloat16_rn(v.x - __bfloat162float(h0)),
                           __float2bfloat16_rn(v.y - __bfloat162float(h1))};
    }
    m0 *= (1.0f / LL); m1 *= (1.0f / LL);
    __nv_bfloat16 h0 = __float2bfloat16_rn(m0);
    __nv_bfloat16 h1 = __float2bfloat16_rn(m1);
    *(__nv_bfloat162*)(g_akvh + obase + (size_t)LL * CCH) = __nv_bfloat162{h0, h1};
    *(__nv_bfloat162*)(g_akvl + obase + (size_t)LL * CCH) =
        __nv_bfloat162{__float2bfloat16_rn(m0 - __bfloat162float(h0)),
                       __float2bfloat16_rn(m1 - __bfloat162float(h1))};
}

// ---------------- 2) weight transpose + split: w[512][N] -> wT[N][512] hi/lo ----
__global__ void wprep(const float* __restrict__ w, __nv_bfloat16* __restrict__ oh,
                      __nv_bfloat16* __restrict__ ol, int N) {
    __shared__ float t[32][33];
    int n0 = blockIdx.x * 32, k0 = blockIdx.y * 32;
    int tx = threadIdx.x, ty = threadIdx.y;     // (32, 8)
#pragma unroll
    for (int j = 0; j < 4; j++)
        t[ty * 4 + j][tx] = w[(size_t)(k0 + ty * 4 + j) * N + n0 + tx];
    __syncthreads();
#pragma unroll
    for (int j = 0; j < 4; j++) {
        float v = t[tx][ty * 4 + j];
        __nv_bfloat16 hi = __float2bfloat16_rn(v);
        __nv_bfloat16 lo = __float2bfloat16_rn(v - __bfloat162float(hi));
        size_t idx = (size_t)(n0 + ty * 4 + j) * CCH + k0 + tx;
        oh[idx] = hi; ol[idx] = lo;
    }
}

// ---------------- 3) split-bf16 3-pass GEMM via mma.sync ---------------------
// C[M][NT] = A[M][512] @ W[NT][512]^T + bias.  CTA 128x128, 8 warps (4M x 2N),
// warp tile 32x64, K-chunk 64, 3-stage cp.async pipeline (loads 2 chunks ahead).
// Stage layout (64 KB): Ah @0, Al @16K, Bh @32K, Bl @48K; rows 128B, XOR-swizzled.
#define GSTAGE 65536
#define GEMM_SMEM (3 * GSTAGE)

template <int NT>
__global__ __launch_bounds__(256)
void gemm_mma3(const __nv_bfloat16* __restrict__ Ah, const __nv_bfloat16* __restrict__ Al,
               const __nv_bfloat16* __restrict__ Wh, const __nv_bfloat16* __restrict__ Wl,
               const float* __restrict__ bias, float* __restrict__ C) {
    extern __shared__ __align__(16) char smem[];
    uint32_t sb = smem_u32(smem);
    int tid = threadIdx.x, lane = tid & 31, wid = tid >> 5;
    int g = lane >> 2, t4 = lane & 3;
    int wm = (wid >> 1) * 32, wn = (wid & 1) * 64;
    size_t m0 = (size_t)blockIdx.y * 128;
    int n0 = blockIdx.x * 128;

    float acc[2][8][4];
#pragma unroll
    for (int i = 0; i < 2; i++)
#pragma unroll
        for (int j = 0; j < 8; j++)
#pragma unroll
            for (int q = 0; q < 4; q++) acc[i][j][q] = 0.f;

    // loader slots: 4 x 16B per thread per tile
    uint32_t soff[4];
    size_t aoff[4], boff[4];
#pragma unroll
    for (int i = 0; i < 4; i++) {
        int l = tid + i * 256;            // 0..1023
        int row = l >> 3, ch = l & 7;
        soff[i] = (uint32_t)(row * 128 + ((ch ^ (row & 7)) << 4));
        aoff[i] = (m0 + row) * CCH + ch * 8;
        boff[i] = (size_t)(n0 + row) * CCH + ch * 8;
    }

    // ldmatrix lane addressing
    int lt = lane >> 3, lr = lane & 7;
    int amrow[2];
#pragma unroll
    for (int mi = 0; mi < 2; mi++) amrow[mi] = wm + mi * 16 + ((lt & 1) << 3) + lr;
    int a_chadd = lt >> 1;
    int bnrow[4];
#pragma unroll
    for (int bb = 0; bb < 4; bb++) bnrow[bb] = wn + bb * 16 + ((lt >> 1) << 3) + lr;
    int b_chadd = lt & 1;

#define LOAD_STAGE(stg, ko)                                                        \
    {                                                                              \
        uint32_t st_ = sb + (uint32_t)(stg) * GSTAGE;                              \
        _Pragma("unroll")                                                          \
        for (int i_ = 0; i_ < 4; i_++) {                                           \
            cp16(st_ + soff[i_],          Ah + aoff[i_] + (ko));                   \
            cp16(st_ + 16384 + soff[i_],  Al + aoff[i_] + (ko));                   \
            cp16(st_ + 32768 + soff[i_],  Wh + boff[i_] + (ko));                   \
            cp16(st_ + 49152 + soff[i_],  Wl + boff[i_] + (ko));                   \
        }                                                                          \
        asm volatile("cp.async.commit_group;" ::: "memory");                       \
    }

    LOAD_STAGE(0, 0);
    LOAD_STAGE(1, 64);

    for (int c = 0; c < 8; c++) {
        // chunk c's group complete when at most 1 newer group remains (c<7);
        // at c==7 nothing newer exists.
        if (c == 7) asm volatile("cp.async.wait_group 0;" ::: "memory");
        else        asm volatile("cp.async.wait_group 1;" ::: "memory");
        __syncthreads();

        uint32_t st = sb + (uint32_t)(c % 3) * GSTAGE;
#pragma unroll
        for (int ks = 0; ks < 4; ks++) {
            int cb = ks * 2;
            uint32_t ah[2][4], al[2][4], bh[8][2], bl[8][2];
#pragma unroll
            for (int mi = 0; mi < 2; mi++) {
                int r = amrow[mi];
                uint32_t ad = st + r * 128 + (((cb + a_chadd) ^ (r & 7)) << 4);
                ldsm4(ah[mi], ad);
                ldsm4(al[mi], ad + 16384);
            }
#pragma unroll
            for (int bb = 0; bb < 4; bb++) {
                int r = bnrow[bb];
                uint32_t bd = st + 32768 + r * 128 + (((cb + b_chadd) ^ (r & 7)) << 4);
                uint32_t rr[4];
                ldsm4(rr, bd);
                bh[2 * bb][0] = rr[0]; bh[2 * bb][1] = rr[1];
                bh[2 * bb + 1][0] = rr[2]; bh[2 * bb + 1][1] = rr[3];
                ldsm4(rr, bd + 16384);
                bl[2 * bb][0] = rr[0]; bl[2 * bb][1] = rr[1];
                bl[2 * bb + 1][0] = rr[2]; bl[2 * bb + 1][1] = rr[3];
            }
#pragma unroll
            for (int mi = 0; mi < 2; mi++)
#pragma unroll
                for (int ni = 0; ni < 8; ni++) {
                    mma16816(acc[mi][ni], ah[mi], bh[ni]);
                    mma16816(acc[mi][ni], ah[mi], bl[ni]);
                    mma16816(acc[mi][ni], al[mi], bh[ni]);
                }
        }
        // stage (c-1)%3's consumers all passed the sync above; refill it with c+2
        if (c + 2 < 8) LOAD_STAGE((c + 2) % 3, (c + 2) * 64);
    }

    // epilogue: bias + fp32 store
#pragma unroll
    for (int ni = 0; ni < 8; ni++) {
        int col = n0 + wn + ni * 8 + t4 * 2;
        float b0 = bias[col], b1 = bias[col + 1];
#pragma unroll
        for (int mi = 0; mi < 2; mi++) {
            size_t r0 = m0 + wm + mi * 16 + g;
            float2 v0 = make_float2(acc[mi][ni][0] + b0, acc[mi][ni][1] + b1);
            float2 v1 = make_float2(acc[mi][ni][2] + b0, acc[mi][ni][3] + b1);
            *(float2*)(C + r0 * NT + col)       = v0;
            *(float2*)(C + (r0 + 8) * NT + col) = v1;
        }
    }
}

// ---------------- 4) attention (fp32; emits bf16 hi/lo for proj) -------------
#define KS_FLOATS (65 * 65 + 3)
#define ATTN_SMEM_FLOATS (64 * 64 + KS_FLOATS + 65 * 64 + 64 * 66)

__global__ void attn_kernel(const int* __restrict__ mask,
                            const float* __restrict__ ef) {
    extern __shared__ float sm[];
    float* qs = sm;
    float* ks = qs + 64 * 64;
    float* vs = ks + KS_FLOATS;
    float* ps = vs + 65 * 64;

    int bh  = blockIdx.x;
    int hd  = bh & (HH - 1);
    int blk = bh >> 3;
    int nb  = blk & (NBLK - 1);
    int tid = threadIdx.x;
    int w   = tid >> 5;
    int lane = tid & 31;

    const float* qbase = g_qkv + (size_t)blk * 65 * 1536 + hd * 64;
    const float* kbase = qbase + 512;
    const float* vbase = qbase + 1024;

    for (int idx = tid; idx < 64 * 16; idx += 256) {
        int r = idx >> 4, c4 = (idx & 15) << 2;
        *(float4*)(qs + r * 64 + c4) = *(const float4*)(qbase + (size_t)r * 1536 + c4);
    }
    for (int idx = tid; idx < 65 * 16; idx += 256) {
        int r = idx >> 4, c4 = (idx & 15) << 2;
        float4 v = *(const float4*)(kbase + (size_t)r * 1536 + c4);
        float* d = ks + r * 65 + c4;
        d[0] = v.x; d[1] = v.y; d[2] = v.z; d[3] = v.w;
    }
    for (int idx = tid; idx < 65 * 16; idx += 256) {
        int r = idx >> 4, c4 = (idx & 15) << 2;
        *(float4*)(vs + r * 64 + c4) = *(const float4*)(vbase + (size_t)r * 1536 + c4);
    }
    __syncthreads();

    int j0 = lane, j1 = lane + 32;
    float acc0[8], acc1[8];
#pragma unroll
    for (int r = 0; r < 8; r++) { acc0[r] = 0.f; acc1[r] = 0.f; }

    // j=64 (block-node) column: shuffle-reduced dot, once per row
    float s2v[8];
    {
        float k64a = ks[64 * 65 + lane];
        float k64b = ks[64 * 65 + lane + 32];
#pragma unroll
        for (int r = 0; r < 8; r++) {
            int i = w * 8 + r;
            float part = qs[i * 64 + lane] * k64a + qs[i * 64 + lane + 32] * k64b;
#pragma unroll
            for (int o = 16; o > 0; o >>= 1) part += __shfl_xor_sync(0xffffffffu, part, o);
            s2v[r] = fmaf(part, SCALE, 1.0f);   // mask forced true, bias 1
        }
    }

    for (int kk = 0; kk < 64; kk++) {
        float k0v = ks[j0 * 65 + kk];
        float k1v = ks[j1 * 65 + kk];
#pragma unroll
        for (int r = 0; r < 8; r++) {
            float qv = qs[(w * 8 + r) * 64 + kk];
            acc0[r] = fmaf(qv, k0v, acc0[r]);
            acc1[r] = fmaf(qv, k1v, acc1[r]);
        }
    }

#pragma unroll
    for (int r = 0; r < 8; r++) {
        int i = w * 8 + r;
        size_t mbase = ((size_t)nb * 64 + i) * 65;
        float b0 = (j0 == i) ? 1.0f : ef[(mbase + j0) * 4 + 3];
        float b1 = (j1 == i) ? 1.0f : ef[(mbase + j1) * 4 + 3];
        float s0 = (mask[mbase + j0] != 0) ? fmaf(acc0[r], SCALE, b0) : -1e9f;
        float s1 = (mask[mbase + j1] != 0) ? fmaf(acc1[r], SCALE, b1) : -1e9f;
        float s2 = s2v[r];

        float m = fmaxf(fmaxf(s0, s1), s2);
#pragma unroll
        for (int o = 16; o > 0; o >>= 1) m = fmaxf(m, __shfl_xor_sync(0xffffffffu, m, o));
        float e0 = __expf(s0 - m), e1 = __expf(s1 - m), e2 = __expf(s2 - m);
        float sum = e0 + e1;
#pragma unroll
        for (int o = 16; o > 0; o >>= 1) sum += __shfl_xor_sync(0xffffffffu, sum, o);
        sum += e2;
        float inv = 1.0f / sum;
        float* prow = ps + i * 66;
        prow[j0] = e0 * inv;
        prow[j1] = e1 * inv;
        if (lane == 0) prow[64] = e2 * inv;
    }
    __syncwarp();

    float o0[8], o1[8];
#pragma unroll
    for (int r = 0; r < 8; r++) { o0[r] = 0.f; o1[r] = 0.f; }
    for (int j = 0; j < 65; j++) {
        float v0 = vs[j * 64 + lane];
        float v1 = vs[j * 64 + lane + 32];
#pragma unroll
        for (int r = 0; r < 8; r++) {
            float p = ps[(w * 8 + r) * 66 + j];
            o0[r] = fmaf(p, v0, o0[r]);
            o1[r] = fmaf(p, v1, o1[r]);
        }
    }
#pragma unroll
    for (int r = 0; r < 8; r++) {
        size_t orow = (size_t)blk * 64 + (w * 8 + r);
        size_t c0 = orow * 512 + hd * 64 + lane;
        float va = o0[r], vb = o1[r];
        __nv_bfloat16 ha = __float2bfloat16_rn(va);
        __nv_bfloat16 hb = __float2bfloat16_rn(vb);
        g_aoh[c0]      = ha;
        g_aoh[c0 + 32] = hb;
        g_aol[c0]      = __float2bfloat16_rn(va - __bfloat162float(ha));
        g_aol[c0 + 32] = __float2bfloat16_rn(vb - __bfloat162float(hb));
    }
}

// ---------------------------------------------------------------------------
extern "C" void kernel_launch(void* const* d_in, const int* in_sizes, int n_in,
                              void* d_out, int out_size) {
    const float* x      = (const float*)d_in[0];
    const int*   mask   = (const int*)d_in[1];
    const float* ef     = (const float*)d_in[2];
    const float* qkv_w  = (const float*)d_in[3];
    const float* qkv_b  = (const float*)d_in[4];
    const float* proj_w = (const float*)d_in[5];
    const float* proj_b = (const float*)d_in[6];
    float*       out    = (float*)d_out;
    (void)in_sizes; (void)n_in; (void)out_size;

    const int ATTN_SMEM = ATTN_SMEM_FLOATS * 4;
    cudaFuncSetAttribute(attn_kernel, cudaFuncAttributeMaxDynamicSharedMemorySize, ATTN_SMEM);
    cudaFuncSetAttribute(gemm_mma3<1536>, cudaFuncAttributeMaxDynamicSharedMemorySize, GEMM_SMEM);
    cudaFuncSetAttribute(gemm_mma3<512>,  cudaFuncAttributeMaxDynamicSharedMemorySize, GEMM_SMEM);

    __nv_bfloat16 *akvh, *akvl, *aoh, *aol, *wqh, *wql, *wph, *wpl;
    cudaGetSymbolAddress((void**)&akvh, g_akvh);
    cudaGetSymbolAddress((void**)&akvl, g_akvl);
    cudaGetSymbolAddress((void**)&aoh,  g_aoh);
    cudaGetSymbolAddress((void**)&aol,  g_aol);
    cudaGetSymbolAddress((void**)&wqh,  g_wqkvTh);
    cudaGetSymbolAddress((void**)&wql,  g_wqkvTl);
    cudaGetSymbolAddress((void**)&wph,  g_wprojTh);
    cudaGetSymbolAddress((void**)&wpl,  g_wprojTl);
    float* qkv;
    cudaGetSymbolAddress((void**)&qkv, g_qkv);

    kvprep2<<<BB * NBLK, 256>>>(x);
    wprep<<<dim3(48, 16), dim3(32, 8)>>>(qkv_w, wqh, wql, 1536);
    wprep<<<dim3(16, 16), dim3(32, 8)>>>(proj_w, wph, wpl, 512);
    // QKV: M = 66560 = 520*128, N = 1536 = 12*128
    gemm_mma3<1536><<<dim3(12, 520), 256, GEMM_SMEM>>>(akvh, akvl, wqh, wql, qkv_b, qkv);
    attn_kernel<<<BB * NBLK * HH, 256, ATTN_SMEM>>>(mask, ef);
    // proj: M = 65536 = 512*128, N = 512 = 4*128
    gemm_mma3<512><<<dim3(4, 512), 256, GEMM_SMEM>>>(aoh, aol, wph, wpl, proj_b, out);
}

// round 15
// speedup vs baseline: 2.6498x; 1.0380x over previous
#include <cuda_runtime.h>
#include <cuda_bf16.h>
#include <cstdint>
#include <math.h>

#define BB   4
#define NBLK 256
#define LL   64
#define KK   65
#define CCH  512
#define HH   8
#define SCALE 0.125f

// ---------------- scratch (device globals; 16B aligned) ----------------
__device__ __align__(16) float g_qkv[(size_t)BB * NBLK * KK * 3 * CCH];      // 409 MB
__device__ __align__(16) __nv_bfloat16 g_akvh[(size_t)BB * NBLK * KK * CCH]; // 68 MB
__device__ __align__(16) __nv_bfloat16 g_akvl[(size_t)BB * NBLK * KK * CCH];
__device__ __align__(16) __nv_bfloat16 g_aoh[(size_t)BB * NBLK * LL * CCH];  // 67 MB
__device__ __align__(16) __nv_bfloat16 g_aol[(size_t)BB * NBLK * LL * CCH];
__device__ __align__(16) __nv_bfloat16 g_wqkvTh[3 * CCH * CCH];              // [1536][512]
__device__ __align__(16) __nv_bfloat16 g_wqkvTl[3 * CCH * CCH];
__device__ __align__(16) __nv_bfloat16 g_wprojTh[CCH * CCH];                 // [512][512]
__device__ __align__(16) __nv_bfloat16 g_wprojTl[CCH * CCH];

// ---------------- helpers (sm_80-era instructions only: compile-safe) -------
__device__ __forceinline__ uint32_t smem_u32(const void* p) {
    uint32_t a;
    asm("{ .reg .u64 t; cvta.to.shared.u64 t, %1; cvt.u32.u64 %0, t; }" : "=r"(a) : "l"(p));
    return a;
}
__device__ __forceinline__ void cp16(uint32_t s, const void* g) {
    asm volatile("cp.async.cg.shared.global [%0], [%1], 16;" :: "r"(s), "l"(g));
}
__device__ __forceinline__ void ldsm4(uint32_t* r, uint32_t a) {
    asm volatile("ldmatrix.sync.aligned.m8n8.x4.shared.b16 {%0,%1,%2,%3}, [%4];"
        : "=r"(r[0]), "=r"(r[1]), "=r"(r[2]), "=r"(r[3]) : "r"(a));
}
__device__ __forceinline__ void mma16816(float* d, const uint32_t* a, const uint32_t* b) {
    asm volatile("mma.sync.aligned.m16n8k16.row.col.f32.bf16.bf16.f32 "
        "{%0,%1,%2,%3}, {%4,%5,%6,%7}, {%8,%9}, {%0,%1,%2,%3};"
        : "+f"(d[0]), "+f"(d[1]), "+f"(d[2]), "+f"(d[3])
        : "r"(a[0]), "r"(a[1]), "r"(a[2]), "r"(a[3]), "r"(b[0]), "r"(b[1]));
}

// ---------------- 1) fused mean + kv split: one CTA per (b,nb) block ---------
__global__ void kvprep2(const float* __restrict__ x) {
    int blk = blockIdx.x;                   // 0..1023
    int t = threadIdx.x;                    // 0..255
    const float* xb = x + (size_t)blk * LL * CCH + t * 2;
    size_t obase = (size_t)blk * KK * CCH + t * 2;
    float m0 = 0.f, m1 = 0.f;
#pragma unroll 4
    for (int r = 0; r < LL; r++) {
        float2 v = *(const float2*)(xb + (size_t)r * CCH);
        m0 += v.x; m1 += v.y;
        __nv_bfloat16 h0 = __float2bfloat16_rn(v.x);
        __nv_bfloat16 h1 = __float2bfloat16_rn(v.y);
        *(__nv_bfloat162*)(g_akvh + obase + (size_t)r * CCH) = __nv_bfloat162{h0, h1};
        *(__nv_bfloat162*)(g_akvl + obase + (size_t)r * CCH) =
            __nv_bfloat162{__float2bfloat16_rn(v.x - __bfloat162float(h0)),
                           __float2bfloat16_rn(v.y - __bfloat162float(h1))};
    }
    m0 *= (1.0f / LL); m1 *= (1.0f / LL);
    __nv_bfloat16 h0 = __float2bfloat16_rn(m0);
    __nv_bfloat16 h1 = __float2bfloat16_rn(m1);
    *(__nv_bfloat162*)(g_akvh + obase + (size_t)LL * CCH) = __nv_bfloat162{h0, h1};
    *(__nv_bfloat162*)(g_akvl + obase + (size_t)LL * CCH) =
        __nv_bfloat162{__float2bfloat16_rn(m0 - __bfloat162float(h0)),
                       __float2bfloat16_rn(m1 - __bfloat162float(h1))};
}

// ---------------- 2) weight transpose + split: w[512][N] -> wT[N][512] hi/lo ----
__global__ void wprep(const float* __restrict__ w, __nv_bfloat16* __restrict__ oh,
                      __nv_bfloat16* __restrict__ ol, int N) {
    __shared__ float t[32][33];
    int n0 = blockIdx.x * 32, k0 = blockIdx.y * 32;
    int tx = threadIdx.x, ty = threadIdx.y;     // (32, 8)
#pragma unroll
    for (int j = 0; j < 4; j++)
        t[ty * 4 + j][tx] = w[(size_t)(k0 + ty * 4 + j) * N + n0 + tx];
    __syncthreads();
#pragma unroll
    for (int j = 0; j < 4; j++) {
        float v = t[tx][ty * 4 + j];
        __nv_bfloat16 hi = __float2bfloat16_rn(v);
        __nv_bfloat16 lo = __float2bfloat16_rn(v - __bfloat162float(hi));
        size_t idx = (size_t)(n0 + ty * 4 + j) * CCH + k0 + tx;
        oh[idx] = hi; ol[idx] = lo;
    }
}

// ---------------- 3) split-bf16 3-pass GEMM via mma.sync ---------------------
// C[M][NT] = A[M][512] @ W[NT][512]^T + bias.
// CTA tile 128(M) x 256(N), 512 threads = 16 warps (4M x 4N), warp tile 32x64.
// K-chunk 64, 2-stage cp.async pipeline; next-chunk loads issued BEFORE mma.
// Stage (96 KB): Ah @0 (16K), Al @16K, Bh @32K (32K), Bl @64K. 128B rows, XOR swizzle.
#define GSTAGE (96 * 1024)
#define GEMM_SMEM (2 * GSTAGE)

template <int NT>
__global__ __launch_bounds__(512)
void gemm_mma3(const __nv_bfloat16* __restrict__ Ah, const __nv_bfloat16* __restrict__ Al,
               const __nv_bfloat16* __restrict__ Wh, const __nv_bfloat16* __restrict__ Wl,
               const float* __restrict__ bias, float* __restrict__ C) {
    extern __shared__ __align__(16) char smem[];
    uint32_t sb = smem_u32(smem);
    int tid = threadIdx.x, lane = tid & 31, wid = tid >> 5;
    int g = lane >> 2, t4 = lane & 3;
    int wm = (wid >> 2) * 32;            // 4 M-warps
    int wn = (wid & 3) * 64;             // 4 N-warps
    size_t m0 = (size_t)blockIdx.y * 128;
    int n0 = blockIdx.x * 256;

    float acc[2][8][4];
#pragma unroll
    for (int i = 0; i < 2; i++)
#pragma unroll
        for (int j = 0; j < 8; j++)
#pragma unroll
            for (int q = 0; q < 4; q++) acc[i][j][q] = 0.f;

    // ldmatrix lane addressing
    int lt = lane >> 3, lr = lane & 7;
    int amrow[2];
#pragma unroll
    for (int mi = 0; mi < 2; mi++) amrow[mi] = wm + mi * 16 + ((lt & 1) << 3) + lr;
    int a_chadd = lt >> 1;
    int bnrow[4];
#pragma unroll
    for (int bb = 0; bb < 4; bb++) bnrow[bb] = wn + bb * 16 + ((lt >> 1) << 3) + lr;
    int b_chadd = lt & 1;

    // Loads per stage: A hi/lo 1024 lines each (2/thr), B hi/lo 2048 each (4/thr)
#define LOAD_STAGE(stg, ko)                                                        \
    {                                                                              \
        uint32_t st_ = sb + (uint32_t)(stg) * GSTAGE;                              \
        _Pragma("unroll")                                                          \
        for (int i_ = 0; i_ < 2; i_++) {                                           \
            int l_ = tid + i_ * 512;                                               \
            int row_ = l_ >> 3, ch_ = l_ & 7;                                      \
            uint32_t so_ = (uint32_t)(row_ * 128 + ((ch_ ^ (row_ & 7)) << 4));     \
            size_t ga_ = (m0 + row_) * CCH + (ko) + ch_ * 8;                       \
            cp16(st_ + so_,         Ah + ga_);                                     \
            cp16(st_ + 16384 + so_, Al + ga_);                                     \
        }                                                                          \
        _Pragma("unroll")                                                          \
        for (int i_ = 0; i_ < 4; i_++) {                                           \
            int l_ = tid + i_ * 512;                                               \
            int row_ = l_ >> 3, ch_ = l_ & 7;                                      \
            uint32_t so_ = (uint32_t)(row_ * 128 + ((ch_ ^ (row_ & 7)) << 4));     \
            size_t gb_ = (size_t)(n0 + row_) * CCH + (ko) + ch_ * 8;               \
            cp16(st_ + 32768 + so_, Wh + gb_);                                     \
            cp16(st_ + 65536 + so_, Wl + gb_);                                     \
        }                                                                          \
        asm volatile("cp.async.commit_group;" ::: "memory");                       \
    }

    LOAD_STAGE(0, 0);

    for (int c = 0; c < 8; c++) {
        asm volatile("cp.async.wait_group 0;" ::: "memory");
        __syncthreads();
        // stage (c+1)&1 was fully consumed during chunk c-1 -> refill now so the
        // cp.async overlaps this chunk's mma work.
        if (c < 7) LOAD_STAGE((c + 1) & 1, (c + 1) * 64);

        uint32_t st = sb + (uint32_t)(c & 1) * GSTAGE;
#pragma unroll
        for (int ks = 0; ks < 4; ks++) {
            int cb = ks * 2;
            uint32_t ah[2][4], al[2][4], bfr[8][2];
#pragma unroll
            for (int mi = 0; mi < 2; mi++) {
                int r = amrow[mi];
                uint32_t ad = st + r * 128 + (((cb + a_chadd) ^ (r & 7)) << 4);
                ldsm4(ah[mi], ad);
                ldsm4(al[mi], ad + 16384);
            }
            // phase 1: B-hi -> AhBh + AlBh
#pragma unroll
            for (int bb = 0; bb < 4; bb++) {
                int r = bnrow[bb];
                uint32_t bd = st + 32768 + r * 128 + (((cb + b_chadd) ^ (r & 7)) << 4);
                uint32_t rr[4];
                ldsm4(rr, bd);
                bfr[2 * bb][0] = rr[0]; bfr[2 * bb][1] = rr[1];
                bfr[2 * bb + 1][0] = rr[2]; bfr[2 * bb + 1][1] = rr[3];
            }
#pragma unroll
            for (int mi = 0; mi < 2; mi++)
#pragma unroll
                for (int ni = 0; ni < 8; ni++) {
                    mma16816(acc[mi][ni], ah[mi], bfr[ni]);
                    mma16816(acc[mi][ni], al[mi], bfr[ni]);
                }
            // phase 2: B-lo -> AhBl (reuse bfr)
#pragma unroll
            for (int bb = 0; bb < 4; bb++) {
                int r = bnrow[bb];
                uint32_t bd = st + 65536 + r * 128 + (((cb + b_chadd) ^ (r & 7)) << 4);
                uint32_t rr[4];
                ldsm4(rr, bd);
                bfr[2 * bb][0] = rr[0]; bfr[2 * bb][1] = rr[1];
                bfr[2 * bb + 1][0] = rr[2]; bfr[2 * bb + 1][1] = rr[3];
            }
#pragma unroll
            for (int mi = 0; mi < 2; mi++)
#pragma unroll
                for (int ni = 0; ni < 8; ni++)
                    mma16816(acc[mi][ni], ah[mi], bfr[ni]);
        }
    }

    // epilogue: bias + fp32 store
#pragma unroll
    for (int ni = 0; ni < 8; ni++) {
        int col = n0 + wn + ni * 8 + t4 * 2;
        float b0 = bias[col], b1 = bias[col + 1];
#pragma unroll
        for (int mi = 0; mi < 2; mi++) {
            size_t r0 = m0 + wm + mi * 16 + g;
            float2 v0 = make_float2(acc[mi][ni][0] + b0, acc[mi][ni][1] + b1);
            float2 v1 = make_float2(acc[mi][ni][2] + b0, acc[mi][ni][3] + b1);
            *(float2*)(C + r0 * NT + col)       = v0;
            *(float2*)(C + (r0 + 8) * NT + col) = v1;
        }
    }
}

// ---------------- 4) attention (fp32; emits bf16 hi/lo for proj) -------------
#define KS_FLOATS (65 * 65 + 3)
#define ATTN_SMEM_FLOATS (64 * 64 + KS_FLOATS + 65 * 64 + 64 * 66)

__global__ void attn_kernel(const int* __restrict__ mask,
                            const float* __restrict__ ef) {
    extern __shared__ float sm[];
    float* qs = sm;
    float* ks = qs + 64 * 64;
    float* vs = ks + KS_FLOATS;
    float* ps = vs + 65 * 64;

    int bh  = blockIdx.x;
    int hd  = bh & (HH - 1);
    int blk = bh >> 3;
    int nb  = blk & (NBLK - 1);
    int tid = threadIdx.x;
    int w   = tid >> 5;
    int lane = tid & 31;

    const float* qbase = g_qkv + (size_t)blk * 65 * 1536 + hd * 64;
    const float* kbase = qbase + 512;
    const float* vbase = qbase + 1024;

    for (int idx = tid; idx < 64 * 16; idx += 256) {
        int r = idx >> 4, c4 = (idx & 15) << 2;
        *(float4*)(qs + r * 64 + c4) = *(const float4*)(qbase + (size_t)r * 1536 + c4);
    }
    for (int idx = tid; idx < 65 * 16; idx += 256) {
        int r = idx >> 4, c4 = (idx & 15) << 2;
        float4 v = *(const float4*)(kbase + (size_t)r * 1536 + c4);
        float* d = ks + r * 65 + c4;
        d[0] = v.x; d[1] = v.y; d[2] = v.z; d[3] = v.w;
    }
    for (int idx = tid; idx < 65 * 16; idx += 256) {
        int r = idx >> 4, c4 = (idx & 15) << 2;
        *(float4*)(vs + r * 64 + c4) = *(const float4*)(vbase + (size_t)r * 1536 + c4);
    }
    __syncthreads();

    int j0 = lane, j1 = lane + 32;
    float acc0[8], acc1[8];
#pragma unroll
    for (int r = 0; r < 8; r++) { acc0[r] = 0.f; acc1[r] = 0.f; }

    // j=64 (block-node) column: shuffle-reduced dot, once per row
    float s2v[8];
    {
        float k64a = ks[64 * 65 + lane];
        float k64b = ks[64 * 65 + lane + 32];
#pragma unroll
        for (int r = 0; r < 8; r++) {
            int i = w * 8 + r;
            float part = qs[i * 64 + lane] * k64a + qs[i * 64 + lane + 32] * k64b;
#pragma unroll
            for (int o = 16; o > 0; o >>= 1) part += __shfl_xor_sync(0xffffffffu, part, o);
            s2v[r] = fmaf(part, SCALE, 1.0f);   // mask forced true, bias 1
        }
    }

    for (int kk = 0; kk < 64; kk++) {
        float k0v = ks[j0 * 65 + kk];
        float k1v = ks[j1 * 65 + kk];
#pragma unroll
        for (int r = 0; r < 8; r++) {
            float qv = qs[(w * 8 + r) * 64 + kk];
            acc0[r] = fmaf(qv, k0v, acc0[r]);
            acc1[r] = fmaf(qv, k1v, acc1[r]);
        }
    }

#pragma unroll
    for (int r = 0; r < 8; r++) {
        int i = w * 8 + r;
        size_t mbase = ((size_t)nb * 64 + i) * 65;
        float b0 = (j0 == i) ? 1.0f : ef[(mbase + j0) * 4 + 3];
        float b1 = (j1 == i) ? 1.0f : ef[(mbase + j1) * 4 + 3];
        float s0 = (mask[mbase + j0] != 0) ? fmaf(acc0[r], SCALE, b0) : -1e9f;
        float s1 = (mask[mbase + j1] != 0) ? fmaf(acc1[r], SCALE, b1) : -1e9f;
        float s2 = s2v[r];

        float m = fmaxf(fmaxf(s0, s1), s2);
#pragma unroll
        for (int o = 16; o > 0; o >>= 1) m = fmaxf(m, __shfl_xor_sync(0xffffffffu, m, o));
        float e0 = __expf(s0 - m), e1 = __expf(s1 - m), e2 = __expf(s2 - m);
        float sum = e0 + e1;
#pragma unroll
        for (int o = 16; o > 0; o >>= 1) sum += __shfl_xor_sync(0xffffffffu, sum, o);
        sum += e2;
        float inv = 1.0f / sum;
        float* prow = ps + i * 66;
        prow[j0] = e0 * inv;
        prow[j1] = e1 * inv;
        if (lane == 0) prow[64] = e2 * inv;
    }
    __syncwarp();

    float o0[8], o1[8];
#pragma unroll
    for (int r = 0; r < 8; r++) { o0[r] = 0.f; o1[r] = 0.f; }
    for (int j = 0; j < 65; j++) {
        float v0 = vs[j * 64 + lane];
        float v1 = vs[j * 64 + lane + 32];
#pragma unroll
        for (int r = 0; r < 8; r++) {
            float p = ps[(w * 8 + r) * 66 + j];
            o0[r] = fmaf(p, v0, o0[r]);
            o1[r] = fmaf(p, v1, o1[r]);
        }
    }
#pragma unroll
    for (int r = 0; r < 8; r++) {
        size_t orow = (size_t)blk * 64 + (w * 8 + r);
        size_t c0 = orow * 512 + hd * 64 + lane;
        float va = o0[r], vb = o1[r];
        __nv_bfloat16 ha = __float2bfloat16_rn(va);
        __nv_bfloat16 hb = __float2bfloat16_rn(vb);
        g_aoh[c0]      = ha;
        g_aoh[c0 + 32] = hb;
        g_aol[c0]      = __float2bfloat16_rn(va - __bfloat162float(ha));
        g_aol[c0 + 32] = __float2bfloat16_rn(vb - __bfloat162float(hb));
    }
}

// ---------------------------------------------------------------------------
extern "C" void kernel_launch(void* const* d_in, const int* in_sizes, int n_in,
                              void* d_out, int out_size) {
    const float* x      = (const float*)d_in[0];
    const int*   mask   = (const int*)d_in[1];
    const float* ef     = (const float*)d_in[2];
    const float* qkv_w  = (const float*)d_in[3];
    const float* qkv_b  = (const float*)d_in[4];
    const float* proj_w = (const float*)d_in[5];
    const float* proj_b = (const float*)d_in[6];
    float*       out    = (float*)d_out;
    (void)in_sizes; (void)n_in; (void)out_size;

    const int ATTN_SMEM = ATTN_SMEM_FLOATS * 4;
    cudaFuncSetAttribute(attn_kernel, cudaFuncAttributeMaxDynamicSharedMemorySize, ATTN_SMEM);
    cudaFuncSetAttribute(gemm_mma3<1536>, cudaFuncAttributeMaxDynamicSharedMemorySize, GEMM_SMEM);
    cudaFuncSetAttribute(gemm_mma3<512>,  cudaFuncAttributeMaxDynamicSharedMemorySize, GEMM_SMEM);

    __nv_bfloat16 *akvh, *akvl, *aoh, *aol, *wqh, *wql, *wph, *wpl;
    cudaGetSymbolAddress((void**)&akvh, g_akvh);
    cudaGetSymbolAddress((void**)&akvl, g_akvl);
    cudaGetSymbolAddress((void**)&aoh,  g_aoh);
    cudaGetSymbolAddress((void**)&aol,  g_aol);
    cudaGetSymbolAddress((void**)&wqh,  g_wqkvTh);
    cudaGetSymbolAddress((void**)&wql,  g_wqkvTl);
    cudaGetSymbolAddress((void**)&wph,  g_wprojTh);
    cudaGetSymbolAddress((void**)&wpl,  g_wprojTl);
    float* qkv;
    cudaGetSymbolAddress((void**)&qkv, g_qkv);

    kvprep2<<<BB * NBLK, 256>>>(x);
    wprep<<<dim3(48, 16), dim3(32, 8)>>>(qkv_w, wqh, wql, 1536);
    wprep<<<dim3(16, 16), dim3(32, 8)>>>(proj_w, wph, wpl, 512);
    // QKV: M = 66560 = 520*128, N = 1536 = 6*256
    gemm_mma3<1536><<<dim3(6, 520), 512, GEMM_SMEM>>>(akvh, akvl, wqh, wql, qkv_b, qkv);
    attn_kernel<<<BB * NBLK * HH, 256, ATTN_SMEM>>>(mask, ef);
    // proj: M = 65536 = 512*128, N = 512 = 2*256
    gemm_mma3<512><<<dim3(2, 512), 512, GEMM_SMEM>>>(aoh, aol, wph, wpl, proj_b, out);
}